// round 3
// baseline (speedup 1.0000x reference)
#include <cuda_runtime.h>
#include <cstddef>

// Depthwise 4x4 FIR conv, stride-2 downsample, zero pad (1,1,1,1).
// x: (16,512,64,64) f32 -> out: (16,512,32,32) f32. kernel: (4,4) f32, flipped.
//
// Thread mapping: 2x4 output block (rows 2b,2b+1; cols 4c..4c+3), reading
// 6 input rows x 10 cols. The 12 LDG.128 per thread are issued BRANCH-FREE
// and front-batched (row index clamped to [0,63]; the only two out-of-range
// rows, r=-1 at b==0 and r=64 at b==15, are zeroed in registers afterward).
// Halo columns +/-1 come from neighbor lanes via __shfl width=8.
// No shared memory, no barriers.

#define IN_W 64
#define OUT_W 32

__global__ __launch_bounds__(256)
void upfirdn_down2_kernel(const float* __restrict__ x,
                          const float* __restrict__ k,
                          float* __restrict__ out,
                          int n_planes)
{
    const int tid = threadIdx.x;
    const int c   = tid & 7;          // col group: output cols 4c..4c+3
    const int b   = (tid >> 3) & 15;  // row block: output rows 2b, 2b+1
    const int pl  = tid >> 7;         // plane within CTA (0/1)
    const int plane = blockIdx.x * 2 + pl;
    if (plane >= n_planes) return;

    const float4* __restrict__ xin =
        (const float4*)(x + (size_t)plane * (IN_W * IN_W));

    // ---- Batched, branch-free loads: 12x LDG.128 back-to-back ----
    float4 A[6], B[6];
    #pragma unroll
    for (int j = 0; j < 6; j++) {
        int r  = 4 * b - 1 + j;
        int rc = min(max(r, 0), IN_W - 1);           // always-legal address
        const float4* rp = xin + (size_t)rc * (IN_W / 4) + c * 2;
        A[j] = __ldg(rp);
        B[j] = __ldg(rp + 1);
    }

    // Zero the (at most one) out-of-range row per thread, in registers.
    const float4 z4 = make_float4(0.f, 0.f, 0.f, 0.f);
    if (b == 0)  { A[0] = z4; B[0] = z4; }           // r = -1
    if (b == 15) { A[5] = z4; B[5] = z4; }           // r = 64

    // Flipped weights (true convolution), broadcast loads (hit constant/L2).
    float w[4][4];
    #pragma unroll
    for (int i = 0; i < 4; i++)
        #pragma unroll
        for (int j = 0; j < 4; j++)
            w[i][j] = __ldg(&k[(3 - i) * 4 + (3 - j)]);

    float acc0[4] = {0.f, 0.f, 0.f, 0.f};
    float acc1[4] = {0.f, 0.f, 0.f, 0.f};

    #pragma unroll
    for (int j = 0; j < 6; j++) {
        const float4 a  = A[j];
        const float4 bb = B[j];
        // Halo columns from neighbor lanes (segment width 8 = one row of col-groups).
        float vl = __shfl_up_sync(0xffffffffu, bb.w, 1, 8);   // col 8c-1
        float vr = __shfl_down_sync(0xffffffffu, a.x, 1, 8);  // col 8c+8
        if (c == 0) vl = 0.f;    // left plane edge (zero pad)
        if (c == 7) vr = 0.f;    // right plane edge (zero pad)

        float v[10];
        v[0] = vl;
        v[1] = a.x;  v[2] = a.y;  v[3] = a.z;  v[4] = a.w;
        v[5] = bb.x; v[6] = bb.y; v[7] = bb.z; v[8] = bb.w;
        v[9] = vr;

        // Input row r = 4b-1+j is tap j for output row 2b (j in [0,4)) and
        // tap j-2 for output row 2b+1 (j in [2,6)).
        if (j < 4) {
            #pragma unroll
            for (int xq = 0; xq < 4; xq++)
                #pragma unroll
                for (int t = 0; t < 4; t++)
                    acc0[xq] = fmaf(v[2 * xq + t], w[j][t], acc0[xq]);
        }
        if (j >= 2) {
            #pragma unroll
            for (int xq = 0; xq < 4; xq++)
                #pragma unroll
                for (int t = 0; t < 4; t++)
                    acc1[xq] = fmaf(v[2 * xq + t], w[j - 2][t], acc1[xq]);
        }
    }

    float* o = out + (size_t)plane * (OUT_W * OUT_W) + (2 * b) * OUT_W + c * 4;
    *(float4*)o           = make_float4(acc0[0], acc0[1], acc0[2], acc0[3]);
    *(float4*)(o + OUT_W) = make_float4(acc1[0], acc1[1], acc1[2], acc1[3]);
}

extern "C" void kernel_launch(void* const* d_in, const int* in_sizes, int n_in,
                              void* d_out, int out_size)
{
    int xi = 0, ki = 1;
    if (n_in >= 2 && in_sizes[0] < in_sizes[1]) { xi = 1; ki = 0; }

    const float* x = (const float*)d_in[xi];
    const float* k = (const float*)d_in[ki];
    float* out = (float*)d_out;

    const int n_planes = in_sizes[xi] / (IN_W * IN_W);   // 8192
    const int blocks = (n_planes + 1) / 2;               // 2 planes per CTA

    upfirdn_down2_kernel<<<blocks, 256>>>(x, k, out, n_planes);
}

// round 4
// speedup vs baseline: 1.0581x; 1.0581x over previous
#include <cuda_runtime.h>
#include <cstddef>

// Depthwise 4x4 FIR conv, stride-2 downsample, zero pad (1,1,1,1).
// x: (16,512,64,64) f32 -> out: (16,512,32,32) f32. kernel: (4,4) f32, flipped.
//
// Thread mapping: 2x4 output block (rows 2b,2b+1; cols 4c..4c+3), reading
// 6 input rows x 10 cols. The 12 LDG.128 per thread are issued branch-free
// and must be HELD LIVE simultaneously for MLP=12 — __launch_bounds__(256,2)
// raises the register budget to 128 so ptxas does not re-serialize them
// (at 32 regs it load->consume chains and DRAM never saturates; measured
// 67% in R2/R3). Halo columns via __shfl width=8. No smem, no barriers.

#define IN_W 64
#define OUT_W 32

__global__ __launch_bounds__(256, 2)
void upfirdn_down2_kernel(const float* __restrict__ x,
                          const float* __restrict__ k,
                          float* __restrict__ out,
                          int n_planes)
{
    const int tid = threadIdx.x;
    const int c   = tid & 7;          // col group: output cols 4c..4c+3
    const int b   = (tid >> 3) & 15;  // row block: output rows 2b, 2b+1
    const int pl  = tid >> 7;         // plane within CTA (0/1)
    const int plane = blockIdx.x * 2 + pl;
    if (plane >= n_planes) return;

    // Flipped weights first (independent scalar loads, L2-broadcast).
    float w[4][4];
    #pragma unroll
    for (int i = 0; i < 4; i++)
        #pragma unroll
        for (int j = 0; j < 4; j++)
            w[i][j] = __ldg(&k[(3 - i) * 4 + (3 - j)]);

    const float4* __restrict__ xin =
        (const float4*)(x + (size_t)plane * (IN_W * IN_W));

    // ---- Batched, branch-free loads: 12x LDG.128, all live at once ----
    float4 A[6], B[6];
    #pragma unroll
    for (int j = 0; j < 6; j++) {
        int r  = 4 * b - 1 + j;
        int rc = min(max(r, 0), IN_W - 1);           // always-legal address
        const float4* rp = xin + (size_t)rc * (IN_W / 4) + c * 2;
        A[j] = __ldg(rp);
        B[j] = __ldg(rp + 1);
    }

    // Zero the (at most one) out-of-range row per thread, in registers.
    const float4 z4 = make_float4(0.f, 0.f, 0.f, 0.f);
    if (b == 0)  { A[0] = z4; B[0] = z4; }           // r = -1
    if (b == 15) { A[5] = z4; B[5] = z4; }           // r = 64

    float acc0[4] = {0.f, 0.f, 0.f, 0.f};
    float acc1[4] = {0.f, 0.f, 0.f, 0.f};

    #pragma unroll
    for (int j = 0; j < 6; j++) {
        const float4 a  = A[j];
        const float4 bb = B[j];
        // Halo columns from neighbor lanes (segment width 8 = one row of col-groups).
        float vl = __shfl_up_sync(0xffffffffu, bb.w, 1, 8);   // col 8c-1
        float vr = __shfl_down_sync(0xffffffffu, a.x, 1, 8);  // col 8c+8
        if (c == 0) vl = 0.f;    // left plane edge (zero pad)
        if (c == 7) vr = 0.f;    // right plane edge (zero pad)

        float v[10];
        v[0] = vl;
        v[1] = a.x;  v[2] = a.y;  v[3] = a.z;  v[4] = a.w;
        v[5] = bb.x; v[6] = bb.y; v[7] = bb.z; v[8] = bb.w;
        v[9] = vr;

        // Input row r = 4b-1+j is tap j for output row 2b (j in [0,4)) and
        // tap j-2 for output row 2b+1 (j in [2,6)).
        if (j < 4) {
            #pragma unroll
            for (int xq = 0; xq < 4; xq++)
                #pragma unroll
                for (int t = 0; t < 4; t++)
                    acc0[xq] = fmaf(v[2 * xq + t], w[j][t], acc0[xq]);
        }
        if (j >= 2) {
            #pragma unroll
            for (int xq = 0; xq < 4; xq++)
                #pragma unroll
                for (int t = 0; t < 4; t++)
                    acc1[xq] = fmaf(v[2 * xq + t], w[j - 2][t], acc1[xq]);
        }
    }

    float* o = out + (size_t)plane * (OUT_W * OUT_W) + (2 * b) * OUT_W + c * 4;
    *(float4*)o           = make_float4(acc0[0], acc0[1], acc0[2], acc0[3]);
    *(float4*)(o + OUT_W) = make_float4(acc1[0], acc1[1], acc1[2], acc1[3]);
}

extern "C" void kernel_launch(void* const* d_in, const int* in_sizes, int n_in,
                              void* d_out, int out_size)
{
    int xi = 0, ki = 1;
    if (n_in >= 2 && in_sizes[0] < in_sizes[1]) { xi = 1; ki = 0; }

    const float* x = (const float*)d_in[xi];
    const float* k = (const float*)d_in[ki];
    float* out = (float*)d_out;

    const int n_planes = in_sizes[xi] / (IN_W * IN_W);   // 8192
    const int blocks = (n_planes + 1) / 2;               // 2 planes per CTA

    upfirdn_down2_kernel<<<blocks, 256>>>(x, k, out, n_planes);
}

// round 5
// speedup vs baseline: 1.0789x; 1.0197x over previous
#include <cuda_runtime.h>
#include <cstddef>

// Depthwise 4x4 FIR conv, stride-2 downsample, zero pad (1,1,1,1).
// x: (16,512,64,64) f32 -> out: (16,512,32,32) f32. kernel: (4,4) f32, flipped.
//
// Thread mapping: 2x4 output block (rows 2b,2b+1; cols 4c..4c+3), reading
// 6 input rows x 10 cols. The 12 LDG.128 per thread are issued branch-free
// and held live simultaneously (MLP=12). R4 lesson: at 32-reg budget ptxas
// re-serializes the batch (DRAM 67%); at 128-reg budget it uses 79 regs but
// residency drops to 16 warps/SM and the compute tail leaves the memory pipe
// idle (DRAM 73%). 79 regs fits a 3-CTA budget (85), so __launch_bounds__
// (256,3) keeps MLP=12 AND 24 warps/SM. No smem, no barriers.

#define IN_W 64
#define OUT_W 32

__global__ __launch_bounds__(256, 3)
void upfirdn_down2_kernel(const float* __restrict__ x,
                          const float* __restrict__ k,
                          float* __restrict__ out,
                          int n_planes)
{
    const int tid = threadIdx.x;
    const int c   = tid & 7;          // col group: output cols 4c..4c+3
    const int b   = (tid >> 3) & 15;  // row block: output rows 2b, 2b+1
    const int pl  = tid >> 7;         // plane within CTA (0/1)
    const int plane = blockIdx.x * 2 + pl;
    if (plane >= n_planes) return;

    // Flipped weights first (independent scalar loads, L2-broadcast).
    float w[4][4];
    #pragma unroll
    for (int i = 0; i < 4; i++)
        #pragma unroll
        for (int j = 0; j < 4; j++)
            w[i][j] = __ldg(&k[(3 - i) * 4 + (3 - j)]);

    const float4* __restrict__ xin =
        (const float4*)(x + (size_t)plane * (IN_W * IN_W));

    // ---- Batched, branch-free loads: 12x LDG.128, all live at once ----
    float4 A[6], B[6];
    #pragma unroll
    for (int j = 0; j < 6; j++) {
        int r  = 4 * b - 1 + j;
        int rc = min(max(r, 0), IN_W - 1);           // always-legal address
        const float4* rp = xin + (size_t)rc * (IN_W / 4) + c * 2;
        A[j] = __ldg(rp);
        B[j] = __ldg(rp + 1);
    }

    // Zero the (at most one) out-of-range row per thread, in registers.
    const float4 z4 = make_float4(0.f, 0.f, 0.f, 0.f);
    if (b == 0)  { A[0] = z4; B[0] = z4; }           // r = -1
    if (b == 15) { A[5] = z4; B[5] = z4; }           // r = 64

    float acc0[4] = {0.f, 0.f, 0.f, 0.f};
    float acc1[4] = {0.f, 0.f, 0.f, 0.f};

    #pragma unroll
    for (int j = 0; j < 6; j++) {
        const float4 a  = A[j];
        const float4 bb = B[j];
        // Halo columns from neighbor lanes (segment width 8 = one row of col-groups).
        float vl = __shfl_up_sync(0xffffffffu, bb.w, 1, 8);   // col 8c-1
        float vr = __shfl_down_sync(0xffffffffu, a.x, 1, 8);  // col 8c+8
        if (c == 0) vl = 0.f;    // left plane edge (zero pad)
        if (c == 7) vr = 0.f;    // right plane edge (zero pad)

        float v[10];
        v[0] = vl;
        v[1] = a.x;  v[2] = a.y;  v[3] = a.z;  v[4] = a.w;
        v[5] = bb.x; v[6] = bb.y; v[7] = bb.z; v[8] = bb.w;
        v[9] = vr;

        // Input row r = 4b-1+j is tap j for output row 2b (j in [0,4)) and
        // tap j-2 for output row 2b+1 (j in [2,6)).
        if (j < 4) {
            #pragma unroll
            for (int xq = 0; xq < 4; xq++)
                #pragma unroll
                for (int t = 0; t < 4; t++)
                    acc0[xq] = fmaf(v[2 * xq + t], w[j][t], acc0[xq]);
        }
        if (j >= 2) {
            #pragma unroll
            for (int xq = 0; xq < 4; xq++)
                #pragma unroll
                for (int t = 0; t < 4; t++)
                    acc1[xq] = fmaf(v[2 * xq + t], w[j - 2][t], acc1[xq]);
        }
    }

    float* o = out + (size_t)plane * (OUT_W * OUT_W) + (2 * b) * OUT_W + c * 4;
    *(float4*)o           = make_float4(acc0[0], acc0[1], acc0[2], acc0[3]);
    *(float4*)(o + OUT_W) = make_float4(acc1[0], acc1[1], acc1[2], acc1[3]);
}

extern "C" void kernel_launch(void* const* d_in, const int* in_sizes, int n_in,
                              void* d_out, int out_size)
{
    int xi = 0, ki = 1;
    if (n_in >= 2 && in_sizes[0] < in_sizes[1]) { xi = 1; ki = 0; }

    const float* x = (const float*)d_in[xi];
    const float* k = (const float*)d_in[ki];
    float* out = (float*)d_out;

    const int n_planes = in_sizes[xi] / (IN_W * IN_W);   // 8192
    const int blocks = (n_planes + 1) / 2;               // 2 planes per CTA

    upfirdn_down2_kernel<<<blocks, 256>>>(x, k, out, n_planes);
}